// round 4
// baseline (speedup 1.0000x reference)
#include <cuda_runtime.h>
#include <stdint.h>

// Problem constants (fixed by setup_inputs)
#define BB   128
#define CC   3
#define HH   224
#define WW   224
#define NP   98          // patches per batch image
#define PSZ  16          // patch size
#define MW   7           // mask words per image row: 224/32
#define MASK_WORDS (BB * HH * MW)   // 200704 words = 802816 bytes (L2-resident)

// Scratch bitmask: bit (b,h,w) set => zero that pixel in all channels.
__device__ __align__(16) unsigned g_mask[MASK_WORDS];

// ---------------------------------------------------------------------------
// Kernel 1: clear the mask (uint4-vectorized; 50176 stores)
// ---------------------------------------------------------------------------
__global__ void clear_mask_kernel() {
    int i = blockIdx.x * blockDim.x + threadIdx.x;   // uint4 index
    if (i < MASK_WORDS / 4) {
        reinterpret_cast<uint4*>(g_mask)[i] = make_uint4(0u, 0u, 0u, 0u);
    }
}

// ---------------------------------------------------------------------------
// Kernel 2: set mask bits for each patch.
// One thread per (b, n) patch: compute the 16-bit row pattern once,
// then atomicOr (no return -> REDG) into 1-2 words per row, 16 rows.
// ---------------------------------------------------------------------------
__global__ void set_mask_kernel(const int* __restrict__ px,
                                const int* __restrict__ py) {
    int i = blockIdx.x * blockDim.x + threadIdx.x;   // b*NP + n
    if (i >= BB * NP) return;
    int b = i / NP;

    int x = px[i];                 // top row (H dim), 0..208
    int y = py[i];                 // left col (W dim), 0..208

    int w0 = y >> 5;
    int sh = y & 31;
    unsigned long long bits = 0xFFFFull << sh;       // 16 bits, may span 2 words
    unsigned lo = (unsigned)bits;
    unsigned hi = (unsigned)(bits >> 32);

    unsigned* base = g_mask + ((size_t)b * HH + x) * MW + w0;
    #pragma unroll
    for (int r = 0; r < PSZ; r++) {
        atomicOr(base, lo);
        if (hi) atomicOr(base + 1, hi);
        base += MW;
    }
}

// ---------------------------------------------------------------------------
// Kernel 3: fused apply: out = mask ? 0 : img, float4 per thread.
// grid = (49, 3, 128): blockIdx.z = b, blockIdx.y = c.
// One image plane = 224*224 floats = 12544 float4 = 49 blocks * 256 threads.
// ---------------------------------------------------------------------------
__global__ __launch_bounds__(256) void apply_mask_kernel(
        const float4* __restrict__ img, float4* __restrict__ out) {
    int idx = blockIdx.x * 256 + threadIdx.x;        // 0..12543 (exact)
    int b = blockIdx.z;
    int c = blockIdx.y;

    int h  = idx / (WW / 4);                         // /56
    int w4 = idx - h * (WW / 4);                     // float4 column

    // mask word covering bits w4*4 .. w4*4+3
    unsigned word = g_mask[((size_t)b * HH + h) * MW + (w4 >> 3)];
    unsigned nib  = (word >> ((w4 & 7) * 4)) & 0xFu;

    size_t off = (((size_t)b * CC + c) * HH + h) * (WW / 4) + w4;
    float4 v = img[off];
    if (nib) {
        if (nib & 1u) v.x = 0.0f;
        if (nib & 2u) v.y = 0.0f;
        if (nib & 4u) v.z = 0.0f;
        if (nib & 8u) v.w = 0.0f;
    }
    out[off] = v;
}

// ---------------------------------------------------------------------------
extern "C" void kernel_launch(void* const* d_in, const int* in_sizes, int n_in,
                              void* d_out, int out_size) {
    const float* imgs = (const float*)d_in[0];
    const int*   px   = (const int*)d_in[1];
    const int*   py   = (const int*)d_in[2];
    float*       out  = (float*)d_out;

    // 1) clear mask: 50176 uint4 stores
    clear_mask_kernel<<<(MASK_WORDS / 4 + 255) / 256, 256>>>();

    // 2) set mask: 12544 patch threads
    set_mask_kernel<<<(BB * NP + 255) / 256, 256>>>(px, py);

    // 3) fused apply
    dim3 grid(49, CC, BB);
    apply_mask_kernel<<<grid, 256>>>((const float4*)imgs, (float4*)out);
}

// round 5
// speedup vs baseline: 1.1092x; 1.1092x over previous
#include <cuda_runtime.h>
#include <stdint.h>

// Problem constants (fixed by setup_inputs)
#define BB     128
#define CC     3
#define HH     224
#define WW     224
#define NP     98        // patches per batch image
#define PSZ    16        // patch size
#define MW     7         // mask words per image row: 224/32
#define STRIPE 16        // rows per block
#define W4     (WW / 4)  // 56 float4 per row
#define PER_BLOCK (STRIPE * W4 * CC)   // 2688 float4 per block

// ---------------------------------------------------------------------------
// Single fused kernel.
// grid = (HH/STRIPE, BB) = (14, 128); block = 256 threads.
// Phase 1: build the 16-row x 7-word occlusion bitmask for this stripe in
//          shared memory from the 98 patch corners of batch image b.
// Phase 2: stream 16 rows x 3 channels of the image through registers,
//          zeroing masked lanes. Fully unrolled so LDG.128s are batched.
// ---------------------------------------------------------------------------
__global__ __launch_bounds__(256) void occlude_kernel(
        const float4* __restrict__ img,
        const int*    __restrict__ px,
        const int*    __restrict__ py,
        float4*       __restrict__ out) {
    __shared__ unsigned mask[STRIPE * MW];   // 112 words

    const int tid = threadIdx.x;
    const int b   = blockIdx.y;
    const int r0  = blockIdx.x * STRIPE;     // first image row of this stripe

    // --- Phase 0: clear smem mask ---
    if (tid < STRIPE * MW) mask[tid] = 0u;
    __syncthreads();

    // --- Phase 1: rasterize intersecting patches into the smem mask ---
    if (tid < NP) {
        int x = px[b * NP + tid];            // top row of patch (H dim)
        int lo_r = max(x, r0);
        int hi_r = min(x + PSZ, r0 + STRIPE);   // exclusive
        if (lo_r < hi_r) {
            int y  = py[b * NP + tid];       // left col of patch (W dim)
            int w0 = y >> 5;
            int sh = y & 31;
            unsigned long long bits = 0xFFFFull << sh;  // spans <=2 words
            unsigned blo = (unsigned)bits;
            unsigned bhi = (unsigned)(bits >> 32);
            for (int rr = lo_r; rr < hi_r; rr++) {
                unsigned* row = mask + (rr - r0) * MW + w0;
                atomicOr(row, blo);
                if (bhi) atomicOr(row + 1, bhi);
            }
        }
    }
    __syncthreads();

    // --- Phase 2: apply mask while streaming img -> out ---
    const size_t img_f4_per_plane = (size_t)HH * W4;       // 12544
    const size_t base = ((size_t)b * CC) * img_f4_per_plane + (size_t)r0 * W4;

    auto process = [&](int i) {
        int c   = i / (STRIPE * W4);            // 0..2  (i / 896)
        int rem = i - c * (STRIPE * W4);
        int r   = rem / W4;                     // 0..15
        int w4  = rem - r * W4;                 // 0..55

        unsigned word = mask[r * MW + (w4 >> 3)];
        unsigned nib  = (word >> ((w4 & 7) * 4)) & 0xFu;

        size_t off = base + (size_t)c * img_f4_per_plane + (size_t)r * W4 + w4;
        float4 v = img[off];
        v.x = (nib & 1u) ? 0.0f : v.x;
        v.y = (nib & 2u) ? 0.0f : v.y;
        v.z = (nib & 4u) ? 0.0f : v.z;
        v.w = (nib & 8u) ? 0.0f : v.w;
        out[off] = v;
    };

    // 2688 = 10 * 256 + 128 : full unroll so loads batch (high MLP)
    #pragma unroll
    for (int k = 0; k < 10; k++) {
        process(tid + k * 256);
    }
    if (tid < 128) process(tid + 2560);
}

// ---------------------------------------------------------------------------
extern "C" void kernel_launch(void* const* d_in, const int* in_sizes, int n_in,
                              void* d_out, int out_size) {
    const float* imgs = (const float*)d_in[0];
    const int*   px   = (const int*)d_in[1];
    const int*   py   = (const int*)d_in[2];
    float*       out  = (float*)d_out;

    dim3 grid(HH / STRIPE, BB);   // (14, 128) = 1792 blocks
    occlude_kernel<<<grid, 256>>>((const float4*)imgs, px, py, (float4*)out);
}

// round 6
// speedup vs baseline: 1.1266x; 1.0157x over previous
#include <cuda_runtime.h>
#include <stdint.h>

// Problem constants (fixed by setup_inputs)
#define BB     128
#define CC     3
#define HH     224
#define WW     224
#define NP     98        // patches per batch image
#define PSZ    16        // patch size
#define MW     7         // mask words per image row: 224/32
#define STRIPE 16        // rows per block
#define W4     (WW / 4)  // 56 float4 per row
#define PER_BLOCK (STRIPE * W4 * CC)   // 2688 float4 per block

// ---------------------------------------------------------------------------
// Single fused kernel.
// grid = (HH/STRIPE, BB) = (14, 128); block = 256 threads.
// Phase 1: build the 16-row x 7-word occlusion bitmask for this stripe in
//          shared memory from the 98 patch corners of batch image b.
// Phase 2: stream 16 rows x 3 channels of the image through registers,
//          zeroing masked lanes. Fully unrolled so LDG.128s are batched.
// ---------------------------------------------------------------------------
__global__ __launch_bounds__(256) void occlude_kernel(
        const float4* __restrict__ img,
        const int*    __restrict__ px,
        const int*    __restrict__ py,
        float4*       __restrict__ out) {
    __shared__ unsigned mask[STRIPE * MW];   // 112 words

    const int tid = threadIdx.x;
    const int b   = blockIdx.y;
    const int r0  = blockIdx.x * STRIPE;     // first image row of this stripe

    // --- Phase 0: clear smem mask ---
    if (tid < STRIPE * MW) mask[tid] = 0u;
    __syncthreads();

    // --- Phase 1: rasterize intersecting patches into the smem mask ---
    if (tid < NP) {
        int x = px[b * NP + tid];            // top row of patch (H dim)
        int lo_r = max(x, r0);
        int hi_r = min(x + PSZ, r0 + STRIPE);   // exclusive
        if (lo_r < hi_r) {
            int y  = py[b * NP + tid];       // left col of patch (W dim)
            int w0 = y >> 5;
            int sh = y & 31;
            unsigned long long bits = 0xFFFFull << sh;  // spans <=2 words
            unsigned blo = (unsigned)bits;
            unsigned bhi = (unsigned)(bits >> 32);
            for (int rr = lo_r; rr < hi_r; rr++) {
                unsigned* row = mask + (rr - r0) * MW + w0;
                atomicOr(row, blo);
                if (bhi) atomicOr(row + 1, bhi);
            }
        }
    }
    __syncthreads();

    // --- Phase 2: apply mask while streaming img -> out ---
    const size_t img_f4_per_plane = (size_t)HH * W4;       // 12544
    const size_t base = ((size_t)b * CC) * img_f4_per_plane + (size_t)r0 * W4;

    auto process = [&](int i) {
        int c   = i / (STRIPE * W4);            // 0..2  (i / 896)
        int rem = i - c * (STRIPE * W4);
        int r   = rem / W4;                     // 0..15
        int w4  = rem - r * W4;                 // 0..55

        unsigned word = mask[r * MW + (w4 >> 3)];
        unsigned nib  = (word >> ((w4 & 7) * 4)) & 0xFu;

        size_t off = base + (size_t)c * img_f4_per_plane + (size_t)r * W4 + w4;
        float4 v = img[off];
        v.x = (nib & 1u) ? 0.0f : v.x;
        v.y = (nib & 2u) ? 0.0f : v.y;
        v.z = (nib & 4u) ? 0.0f : v.z;
        v.w = (nib & 8u) ? 0.0f : v.w;
        out[off] = v;
    };

    // 2688 = 10 * 256 + 128 : full unroll so loads batch (high MLP)
    #pragma unroll
    for (int k = 0; k < 10; k++) {
        process(tid + k * 256);
    }
    if (tid < 128) process(tid + 2560);
}

// ---------------------------------------------------------------------------
extern "C" void kernel_launch(void* const* d_in, const int* in_sizes, int n_in,
                              void* d_out, int out_size) {
    const float* imgs = (const float*)d_in[0];
    const int*   px   = (const int*)d_in[1];
    const int*   py   = (const int*)d_in[2];
    float*       out  = (float*)d_out;

    dim3 grid(HH / STRIPE, BB);   // (14, 128) = 1792 blocks
    occlude_kernel<<<grid, 256>>>((const float4*)imgs, px, py, (float4*)out);
}